// round 1
// baseline (speedup 1.0000x reference)
#include <cuda_runtime.h>

#define NB 2
#define NS 1024
#define FIN 768
#define NE 768
#define NH 12
#define NDH 64
#define NFH 64
#define MIN_POS 1e-6f
#define EPSV 1e-20f

// ---------------- scratch (device globals; no allocation) ----------------
__device__ __align__(16) float g_Wn[NFH * NDH];                 // normalized W [f][d]
__device__ __align__(16) float g_xe[NB * NS * NE];              // clipped embed output
__device__ __align__(16) float g_h[NB * NH * NS * NFH];         // h   [bh][s][f]
__device__ __align__(16) float g_hri[NB * NH * NS * NDH];       // rec*inp [bh][s][d]
__device__ __align__(16) float g_cfin[NB * NE];                 // final mixed row per batch
__device__ __align__(16) float g_yrow[NB * FIN];                // final projected row per batch

// ---------------- helpers ----------------
__device__ __forceinline__ float red16(float v) {
    v += __shfl_xor_sync(0xffffffffu, v, 8);
    v += __shfl_xor_sync(0xffffffffu, v, 4);
    v += __shfl_xor_sync(0xffffffffu, v, 2);
    v += __shfl_xor_sync(0xffffffffu, v, 1);
    return v;
}
__device__ __forceinline__ float red32(float v) {
    v += __shfl_xor_sync(0xffffffffu, v, 16);
    return red16(v);
}

// ---------------- K1: normalize nnmf_w rows ----------------
__global__ void wnorm_kernel(const float* __restrict__ nnmf_w) {
    int f = threadIdx.x;  // 0..63
    float s = 0.f;
#pragma unroll
    for (int d = 0; d < NDH; ++d) s += nnmf_w[f * NDH + d];
    s = fmaxf(s, EPSV);
    float inv = 1.f / s;
#pragma unroll
    for (int d = 0; d < NDH; ++d) g_Wn[f * NDH + d] = nnmf_w[f * NDH + d] * inv;
}

// ---------------- K2: embed GEMM + clip  xe[m][n] = max(x@Ew^T + b, 1e-6) ----------------
// M=2048 (tokens), N=768, K=768. BM=BN=64, BK=16, 256 threads, 4x4 microtile.
__global__ void __launch_bounds__(256) embed_gemm_kernel(const float* __restrict__ X,
                                                         const float* __restrict__ Wm,
                                                         const float* __restrict__ bias) {
    __shared__ __align__(16) float As[16][68];
    __shared__ __align__(16) float Bs[16][68];
    int tid = threadIdx.x;
    int bm = blockIdx.y * 64, bn = blockIdx.x * 64;
    int lk = tid & 15, lr = tid >> 4;  // loader coords
    int ty = tid >> 4, tx = tid & 15;  // compute coords
    float acc[4][4] = {};
    for (int k0 = 0; k0 < FIN; k0 += 16) {
#pragma unroll
        for (int i = 0; i < 4; i++)
            As[lk][lr + i * 16] = X[(size_t)(bm + lr + i * 16) * FIN + k0 + lk];
#pragma unroll
        for (int i = 0; i < 4; i++)
            Bs[lk][lr + i * 16] = Wm[(size_t)(bn + lr + i * 16) * FIN + k0 + lk];
        __syncthreads();
#pragma unroll
        for (int kk = 0; kk < 16; kk++) {
            float4 ra = *(const float4*)&As[kk][ty * 4];
            float4 rb = *(const float4*)&Bs[kk][tx * 4];
            float a[4] = {ra.x, ra.y, ra.z, ra.w};
            float b_[4] = {rb.x, rb.y, rb.z, rb.w};
#pragma unroll
            for (int i = 0; i < 4; i++)
#pragma unroll
                for (int j = 0; j < 4; j++) acc[i][j] += a[i] * b_[j];
        }
        __syncthreads();
    }
#pragma unroll
    for (int i = 0; i < 4; i++) {
        int m = bm + ty * 4 + i;
#pragma unroll
        for (int j = 0; j < 4; j++) {
            int n = bn + tx * 4 + j;
            g_xe[(size_t)m * NE + n] = fmaxf(acc[i][j] + bias[n], MIN_POS);
        }
    }
}

// ---------------- K3: fused NNMF iterations ----------------
// Block: one head x 32 tokens. 256 threads: thread = (tg in 0..15, d4 in 0..15),
// owns tokens t0=2*tg, t1=2*tg+1 and quad d4*4..d4*4+3 (both as d-slice and f-slice).
__global__ void __launch_bounds__(256) nnmf_kernel() {
    __shared__ __align__(16) float sW[NFH * NDH];      // W row-major [f][d]
    __shared__ __align__(16) float s_h[32][64];
    __shared__ __align__(16) float s_ratio[32][64];

    int head = blockIdx.y;
    int tile = blockIdx.x;        // 0..63 (32 tokens each)
    int tid = threadIdx.x;
    int d4 = tid & 15;
    int tg = tid >> 4;
    int t0 = tg * 2, t1 = tg * 2 + 1;
    int tokbase = tile * 32;

    for (int i = tid; i < NFH * NDH; i += 256) sW[i] = g_Wn[i];

    // load + clip already done; compute inp (l1norm over 64)
    float inp0[4], inp1[4];
    {
        const float4 x0 = *(const float4*)&g_xe[(size_t)(tokbase + t0) * NE + head * 64 + d4 * 4];
        const float4 x1 = *(const float4*)&g_xe[(size_t)(tokbase + t1) * NE + head * 64 + d4 * 4];
        float s0 = red16(x0.x + x0.y + x0.z + x0.w);
        float s1 = red16(x1.x + x1.y + x1.z + x1.w);
        float i0 = 1.f / fmaxf(s0, EPSV), i1 = 1.f / fmaxf(s1, EPSV);
        inp0[0] = x0.x * i0; inp0[1] = x0.y * i0; inp0[2] = x0.z * i0; inp0[3] = x0.w * i0;
        inp1[0] = x1.x * i1; inp1[1] = x1.y * i1; inp1[2] = x1.z * i1; inp1[3] = x1.w * i1;
    }
    float hr0[4], hr1[4];
    const float hinit = 1.f / 64.f;
#pragma unroll
    for (int i = 0; i < 4; i++) { hr0[i] = hinit; hr1[i] = hinit; }
    *(float4*)&s_h[t0][d4 * 4] = make_float4(hinit, hinit, hinit, hinit);
    *(float4*)&s_h[t1][d4 * 4] = make_float4(hinit, hinit, hinit, hinit);
    __syncthreads();

    float rn0[4], rn1[4];  // normalized reconstruction (kept for last iter)

    for (int it = 0; it < 3; ++it) {
        // rec-phase: rec[d] = sum_f h[f] * W[f][d]
        float a0[4] = {}, a1[4] = {};
#pragma unroll 16
        for (int ff = 0; ff < 64; ++ff) {
            float4 w = *(const float4*)&sW[ff * 64 + d4 * 4];
            float h0 = s_h[t0][ff], h1 = s_h[t1][ff];
            a0[0] += h0 * w.x; a0[1] += h0 * w.y; a0[2] += h0 * w.z; a0[3] += h0 * w.w;
            a1[0] += h1 * w.x; a1[1] += h1 * w.y; a1[2] += h1 * w.z; a1[3] += h1 * w.w;
        }
#pragma unroll
        for (int i = 0; i < 4; i++) { a0[i] = fmaxf(a0[i], MIN_POS); a1[i] = fmaxf(a1[i], MIN_POS); }
        float p0 = red16(a0[0] + a0[1] + a0[2] + a0[3]);
        float p1 = red16(a1[0] + a1[1] + a1[2] + a1[3]);
        float iv0 = 1.f / fmaxf(p0, EPSV), iv1 = 1.f / fmaxf(p1, EPSV);
        float q0[4], q1[4];
#pragma unroll
        for (int i = 0; i < 4; i++) {
            rn0[i] = a0[i] * iv0; rn1[i] = a1[i] * iv1;
            q0[i] = inp0[i] / rn0[i]; q1[i] = inp1[i] / rn1[i];
        }
        *(float4*)&s_ratio[t0][d4 * 4] = make_float4(q0[0], q0[1], q0[2], q0[3]);
        *(float4*)&s_ratio[t1][d4 * 4] = make_float4(q1[0], q1[1], q1[2], q1[3]);
        __syncthreads();

        // t-phase: t[f] = sum_d ratio[d] * W[f][d]   (f = d4*4+i)
        float b0[4] = {}, b1[4] = {};
#pragma unroll
        for (int jj = 0; jj < 16; ++jj) {
            int j = (jj + d4) & 15;  // stagger to avoid bank conflicts
            float4 r0v = *(const float4*)&s_ratio[t0][j * 4];
            float4 r1v = *(const float4*)&s_ratio[t1][j * 4];
#pragma unroll
            for (int i = 0; i < 4; i++) {
                float4 w = *(const float4*)&sW[(d4 * 4 + i) * 64 + j * 4];
                b0[i] += w.x * r0v.x + w.y * r0v.y + w.z * r0v.z + w.w * r0v.w;
                b1[i] += w.x * r1v.x + w.y * r1v.y + w.z * r1v.z + w.w * r1v.w;
            }
        }
        float hn0[4], hn1[4];
#pragma unroll
        for (int i = 0; i < 4; i++) {
            hn0[i] = fmaxf(hr0[i] * b0[i], MIN_POS);
            hn1[i] = fmaxf(hr1[i] * b1[i], MIN_POS);
        }
        float hs0 = red16(hn0[0] + hn0[1] + hn0[2] + hn0[3]);
        float hs1 = red16(hn1[0] + hn1[1] + hn1[2] + hn1[3]);
        float ih0 = 1.f / fmaxf(hs0, EPSV), ih1 = 1.f / fmaxf(hs1, EPSV);
#pragma unroll
        for (int i = 0; i < 4; i++) { hr0[i] = hn0[i] * ih0; hr1[i] = hn1[i] * ih1; }
        *(float4*)&s_h[t0][d4 * 4] = make_float4(hr0[0], hr0[1], hr0[2], hr0[3]);
        *(float4*)&s_h[t1][d4 * 4] = make_float4(hr1[0], hr1[1], hr1[2], hr1[3]);
        __syncthreads();
    }

    // final l1norm of h (matches reference's extra normalize)
    float hs0 = red16(hr0[0] + hr0[1] + hr0[2] + hr0[3]);
    float hs1 = red16(hr1[0] + hr1[1] + hr1[2] + hr1[3]);
    float ih0 = 1.f / fmaxf(hs0, EPSV), ih1 = 1.f / fmaxf(hs1, EPSV);

    // write outputs in [bh][s][64] layout
    int token0 = tokbase + t0, token1 = tokbase + t1;
    int b0i = token0 >> 10, s0i = token0 & 1023;
    int b1i = token1 >> 10, s1i = token1 & 1023;
    size_t base0 = ((size_t)((b0i * NH + head) * NS + s0i)) * 64 + d4 * 4;
    size_t base1 = ((size_t)((b1i * NH + head) * NS + s1i)) * 64 + d4 * 4;
    *(float4*)&g_h[base0] = make_float4(hr0[0] * ih0, hr0[1] * ih0, hr0[2] * ih0, hr0[3] * ih0);
    *(float4*)&g_h[base1] = make_float4(hr1[0] * ih1, hr1[1] * ih1, hr1[2] * ih1, hr1[3] * ih1);
    *(float4*)&g_hri[base0] = make_float4(rn0[0] * inp0[0], rn0[1] * inp0[1], rn0[2] * inp0[2], rn0[3] * inp0[3]);
    *(float4*)&g_hri[base1] = make_float4(rn1[0] * inp1[0], rn1[1] * inp1[1], rn1[2] * inp1[2], rn1[3] * inp1[3]);
}

// ---------------- K4: collapsed alpha dynamics (one block per (b,head)) ----------------
__global__ void __launch_bounds__(1024) alpha_kernel() {
    __shared__ __align__(16) float s_W[NFH * NDH];
    __shared__ float s_a[NS];
    __shared__ float s_part[1024];
    __shared__ float s_c[64];
    __shared__ float s_ai[64];

    int bh = blockIdx.x;  // 0..23
    int tid = threadIdx.x;
    int p = tid >> 6, f = tid & 63;

    for (int i = tid; i < NFH * NDH; i += 1024) s_W[i] = g_Wn[i];
    s_a[tid] = 1.f;
    __syncthreads();

    const float* hblk = g_h + (size_t)bh * NS * 64;
    const float4* hri = (const float4*)(g_hri + (size_t)bh * NS * 64);

    for (int it = 0; it < 3; ++it) {
        // c[f] = sum_o h[o][f] * a[o]
        float partial = 0.f;
        const float* hb = hblk + (size_t)(p * 64) * 64;
#pragma unroll 8
        for (int oo = 0; oo < 64; ++oo) partial += hb[oo * 64 + f] * s_a[p * 64 + oo];
        s_part[tid] = partial;
        __syncthreads();
        if (tid < 64) {
            float c = 0.f;
#pragma unroll
            for (int p2 = 0; p2 < 16; ++p2) c += s_part[p2 * 64 + tid];
            s_c[tid] = c;
        }
        __syncthreads();
        if (tid < 64) {
            float r = 0.f;
#pragma unroll
            for (int ff = 0; ff < 64; ++ff) r += s_c[ff] * s_W[ff * 64 + tid];
            s_ai[tid] = 1.f / (r + EPSV);
        }
        __syncthreads();
        // u[o] = sum_d hri[o][d] * ai[d];  a[o] *= u[o]
        float u = 0.f;
        const float4* hro = hri + (size_t)tid * 16;
#pragma unroll
        for (int q = 0; q < 16; ++q) {
            float4 v = hro[q];
            u += v.x * s_ai[q * 4] + v.y * s_ai[q * 4 + 1] + v.z * s_ai[q * 4 + 2] + v.w * s_ai[q * 4 + 3];
        }
        s_a[tid] *= u;
        __syncthreads();
    }

    // final c with updated a -> g_cfin[b][head*64+f]
    {
        float partial = 0.f;
        const float* hb = hblk + (size_t)(p * 64) * 64;
#pragma unroll 8
        for (int oo = 0; oo < 64; ++oo) partial += hb[oo * 64 + f] * s_a[p * 64 + oo];
        s_part[tid] = partial;
        __syncthreads();
        if (tid < 64) {
            float c = 0.f;
#pragma unroll
            for (int p2 = 0; p2 < 16; ++p2) c += s_part[p2 * 64 + tid];
            int b = bh / NH, head = bh % NH;
            g_cfin[b * NE + head * 64 + tid] = c;
        }
    }
}

// ---------------- K5: out projection of the 2 unique rows ----------------
// grid (96, 2), 256 threads; warp per output j.
__global__ void __launch_bounds__(256) outrow_kernel(const float* __restrict__ out_w,
                                                     const float* __restrict__ out_b) {
    int b = blockIdx.y;
    int warp = threadIdx.x >> 5, lane = threadIdx.x & 31;
    int j = blockIdx.x * 8 + warp;
    const float* c = g_cfin + b * NE;
    const float* wrow = out_w + (size_t)j * NE;
    float acc = 0.f;
    for (int e = lane; e < NE; e += 32) acc += c[e] * wrow[e];
    acc = red32(acc);
    if (lane == 0) g_yrow[b * FIN + j] = acc + out_b[j];
}

// ---------------- K6: broadcast rows to all positions ----------------
__global__ void __launch_bounds__(256) bcast_kernel(float* __restrict__ out) {
    int idx = blockIdx.x * 256 + threadIdx.x;       // over B*S*192 float4s
    const int per_row = FIN / 4;                    // 192
    int j4 = idx % per_row;
    int bs = idx / per_row;
    int b = bs >> 10;
    float4 v = ((const float4*)(g_yrow + b * FIN))[j4];
    ((float4*)out)[idx] = v;
}

// ---------------- launch ----------------
extern "C" void kernel_launch(void* const* d_in, const int* in_sizes, int n_in,
                              void* d_out, int out_size) {
    const float* x       = (const float*)d_in[0];
    const float* embed_w = (const float*)d_in[1];
    const float* embed_b = (const float*)d_in[2];
    const float* nnmf_w  = (const float*)d_in[3];
    const float* out_w   = (const float*)d_in[4];
    const float* out_b   = (const float*)d_in[5];
    float* out = (float*)d_out;

    wnorm_kernel<<<1, 64>>>(nnmf_w);
    embed_gemm_kernel<<<dim3(NE / 64, (NB * NS) / 64), 256>>>(x, embed_w, embed_b);
    nnmf_kernel<<<dim3((NB * NS) / 32, NH), 256>>>();
    alpha_kernel<<<NB * NH, 1024>>>();
    outrow_kernel<<<dim3(NE / 8, NB), 256>>>(out_w, out_b);
    bcast_kernel<<<(NB * NS * (FIN / 4)) / 256, 256>>>(out);
}